// round 14
// baseline (speedup 1.0000x reference)
#include <cuda_runtime.h>
#include <cstdint>

#define NFACES 1000
#define NPAD   1024
#define IMG    256
#define SPLIT  4
#define CHUNK  256                // 4*256 = 1024 faces padded; 1 face/thread
#define NTILES 256
#define NITEMS (NTILES * SPLIT)   // 1024 items
#define NBLOCKS 1024
#define CULL_T 15.0f              // frag <= 2^-15 dropped (validated: rel_err ~2e-6)
#define ACT_T  (-15.0f)
#define CLAMPF 33554432.0f        // 2^25

__device__ float4   g_c0[NPAD];
__device__ float4   g_c1[NPAD];
__device__ float    g_c2[NPAD];
__device__ int      g_degblk[4];
__device__ float    g_part[SPLIT * IMG * IMG];   // 1 MB
__device__ float    g_row[NTILES];
__device__ unsigned g_tcnt[NTILES];              // wrapping -> replay-safe
__device__ unsigned g_done;
__device__ unsigned g_qhead;

__device__ __forceinline__ float ex2f(float x) {
    float y; asm("ex2.approx.f32 %0, %1;" : "=f"(y) : "f"(x)); return y;
}
__device__ __forceinline__ float rcpaf(float x) {
    float y; asm("rcp.approx.f32 %0, %1;" : "=f"(y) : "f"(x)); return y;
}
__device__ __forceinline__ float rsqaf(float x) {
    float y; asm("rsqrt.approx.f32 %0, %1;" : "=f"(y) : "f"(x)); return y;
}

// ---------------------------------------------------------------------------
// Kernel 1: per-face prep + queue reset
// ---------------------------------------------------------------------------
__global__ void __launch_bounds__(256) prep_kernel(
    const float* __restrict__ verts,
    const int*   __restrict__ faces,
    const float* __restrict__ cam)
{
    __shared__ int wdeg[8];
    const int tid = threadIdx.x;
    const int f   = blockIdx.x * 256 + tid;

    if (blockIdx.x == 0 && tid == 0) g_qhead = 0u;

    bool deg = false;

    if (f < NFACES) {
        float ex = cam[0], ey = cam[1], ez = cam[2];
        float rz = rsqaf(ex*ex + ey*ey + ez*ez);
        float zx = -ex * rz, zy = -ey * rz, zz = -ez * rz;
        float rx = rsqaf(zz*zz + zx*zx);
        float xx = zz * rx, xz = -zx * rx;
        float yx = zy * xz;
        float yy = zz * xx - zx * xz;
        float yz = -zy * xx;

        const float w = 0.57735026918962576f;  // tan(30 deg)

        float px[3], py[3];
        #pragma unroll
        for (int k = 0; k < 3; k++) {
            int vi = faces[3 * f + k];
            float dx = verts[3 * vi + 0] - ex;
            float dy = verts[3 * vi + 1] - ey;
            float dz = verts[3 * vi + 2] - ez;
            float cx = xx * dx + xz * dz;
            float cy = yx * dx + yy * dy + yz * dz;
            float cz = zx * dx + zy * dy + zz * dz;
            float rzw = rcpaf(cz * w);
            px[k] = cx * rzw;
            py[k] = cy * rzw;
        }

        float e01x = px[1] - px[0], e01y = py[1] - py[0];
        float e02x = px[2] - px[0], e02y = py[2] - py[0];
        float area = __fmul_rn(e01x, e02y) - __fmul_rn(e01y, e02x);

        if (area == 0.f) {
            deg = true;
            g_c0[f] = make_float4(0.f, 0.f, 1e9f, 0.f);
            g_c1[f] = make_float4(0.f, 0.f, 0.f, 0.f);
            g_c2[f] = 0.f;
        } else {
            float s = (area > 0.f) ? 1.f : -1.f;
            float K = s * 144.26950408889634f;

            float A[3], B[3], C[3];
            const int ia[3] = {0, 1, 2}, ib[3] = {1, 2, 0};
            #pragma unroll
            for (int e = 0; e < 3; e++) {
                float ax = px[ib[e]] - px[ia[e]];
                float ay = py[ib[e]] - py[ia[e]];
                float rlen = rsqaf(ax*ax + ay*ay);
                float nx = -ay * rlen, ny = ax * rlen;
                A[e] = -K * nx;
                B[e] = -K * ny;
                C[e] =  K * (px[ia[e]] * nx + py[ia[e]] * ny);
            }
            g_c0[f] = make_float4(A[0], B[0], C[0], A[1]);
            g_c1[f] = make_float4(B[1], C[1], A[2], B[2]);
            g_c2[f] = C[2];
        }
    } else {
        g_c0[f] = make_float4(0.f, 0.f, 1e9f, 0.f);
        g_c1[f] = make_float4(0.f, 0.f, 0.f, 0.f);
        g_c2[f] = 0.f;
    }

    unsigned bal = __ballot_sync(0xffffffffu, deg);
    if ((tid & 31) == 0) wdeg[tid >> 5] = __popc(bal);
    __syncthreads();
    if (tid == 0) {
        int nd = 0;
        #pragma unroll
        for (int i = 0; i < 8; i++) nd += wdeg[i];
        g_degblk[blockIdx.x] = nd;
    }
}

// ---------------------------------------------------------------------------
// Kernel 2: work-stealing render. Item = (tile, z); 256 faces classified
// one-per-thread (all warps), compacted into cat lists, then per-pixel math.
// ---------------------------------------------------------------------------
__global__ void __launch_bounds__(256) render_kernel(
    const float* __restrict__ ref,
    float*       __restrict__ out)
{
    __shared__ float4 sL1[CHUNK];          // 1 active edge: (A,B,C,_)
    __shared__ float4 sL2[CHUNK * 2];      // 2 active edges
    __shared__ float4 sL3[CHUNK * 3];      // 3 active edges
    __shared__ int    wc1[8], wc2[8], wc3[8], wcz[8];
    __shared__ int    s_item, s_flag;
    __shared__ float  red[256];

    const int tid  = threadIdx.x;
    const int lane = tid & 31, wid = tid >> 5;
    const unsigned lmask = (1u << lane) - 1u;

    for (;;) {
        if (tid == 0) s_item = (int)atomicAdd(&g_qhead, 1u);
        __syncthreads();
        const int item = s_item;
        if (item >= NITEMS) return;

        const int tileIdx = item >> 2;          // SPLIT = 4
        const int z       = item & (SPLIT - 1);
        const int c0 = (tileIdx & 15) * 16, r0 = (tileIdx >> 4) * 16;

        const float xmin = (2.f * c0 + 1.f)        * (1.f / 256.f) - 1.f;
        const float xmax = (2.f * (c0 + 15) + 1.f) * (1.f / 256.f) - 1.f;
        const float ymax = 1.f - (2.f * r0 + 1.f)        * (1.f / 256.f);
        const float ymin = 1.f - (2.f * (r0 + 15) + 1.f) * (1.f / 256.f);

        // ---------- Phase A: classify 1 face per thread ---------------------
        int  cat = 0;           // 0 dropped, 1/2/3 = #active edges
        bool zero = false;
        float4 E0, E1, E2;
        bool a0 = false, a1 = false, a2 = false;
        {
            const int f = z * CHUNK + tid;
            float4 fa = g_c0[f], fb = g_c1[f];
            float  fcc = g_c2[f];
            E0 = make_float4(fa.x, fa.y, fa.z, 0.f);
            E1 = make_float4(fa.w, fb.x, fb.y, 0.f);
            E2 = make_float4(fb.z, fb.w, fcc,  0.f);

            float m0, M0, m1, M1, m2, M2;
            {
                float xl = E0.x * xmin, xh = E0.x * xmax;
                float yl = E0.y * ymin, yh = E0.y * ymax;
                m0 = fminf(xl, xh) + fminf(yl, yh) + E0.z;
                M0 = fmaxf(xl, xh) + fmaxf(yl, yh) + E0.z;
            }
            {
                float xl = E1.x * xmin, xh = E1.x * xmax;
                float yl = E1.y * ymin, yh = E1.y * ymax;
                m1 = fminf(xl, xh) + fminf(yl, yh) + E1.z;
                M1 = fmaxf(xl, xh) + fmaxf(yl, yh) + E1.z;
            }
            {
                float xl = E2.x * xmin, xh = E2.x * xmax;
                float yl = E2.y * ymin, yh = E2.y * ymax;
                m2 = fminf(xl, xh) + fminf(yl, yh) + E2.z;
                M2 = fmaxf(xl, xh) + fmaxf(yl, yh) + E2.z;
            }
            float q = fmaxf(m0, 0.f) + fmaxf(m1, 0.f) + fmaxf(m2, 0.f);
            if (q < CULL_T) {
                a0 = M0 > ACT_T; a1 = M1 > ACT_T; a2 = M2 > ACT_T;
                int na = (int)a0 + (int)a1 + (int)a2;
                if (na == 0) zero = true;   // face covers tile deeply -> plane 0
                else cat = na;
            }
        }

        unsigned b1 = __ballot_sync(0xffffffffu, cat == 1);
        unsigned b2 = __ballot_sync(0xffffffffu, cat == 2);
        unsigned b3 = __ballot_sync(0xffffffffu, cat == 3);
        unsigned bz = __ballot_sync(0xffffffffu, zero);
        if (lane == 0) {
            wc1[wid] = __popc(b1); wc2[wid] = __popc(b2);
            wc3[wid] = __popc(b3); wcz[wid] = __popc(bz);
        }
        __syncthreads();

        int p1 = 0, p2 = 0, p3 = 0;
        int cnt1 = 0, cnt2 = 0, cnt3 = 0, cntz = 0;
        #pragma unroll
        for (int w2 = 0; w2 < 8; w2++) {
            if (w2 < wid) { p1 += wc1[w2]; p2 += wc2[w2]; p3 += wc3[w2]; }
            cnt1 += wc1[w2]; cnt2 += wc2[w2]; cnt3 += wc3[w2]; cntz += wcz[w2];
        }
        const bool tile_zero = cntz > 0;

        if (!tile_zero) {
            if (cat == 1) {
                int off = p1 + __popc(b1 & lmask);
                sL1[off] = a0 ? E0 : (a1 ? E1 : E2);
            } else if (cat == 2) {
                int off = p2 + __popc(b2 & lmask);
                float4 p, qv;
                if (!a0)      { p = E1; qv = E2; }
                else if (!a1) { p = E0; qv = E2; }
                else          { p = E0; qv = E1; }
                sL2[2*off] = p; sL2[2*off + 1] = qv;
            } else if (cat == 3) {
                int off = p3 + __popc(b3 & lmask);
                sL3[3*off] = E0; sL3[3*off + 1] = E1; sL3[3*off + 2] = E2;
            }
        }
        __syncthreads();

        const int gc = c0 + (tid & 15);
        const int gr = r0 + (tid >> 4);
        const int pix = gr * IMG + gc;

        float prod;
        if (tile_zero) {
            prod = 0.f;                        // a face covers the tile deeply
        } else {
            const float X = (2.f * gc + 1.f) * (1.f / 256.f) - 1.f;
            const float Y = 1.f - (2.f * gr + 1.f) * (1.f / 256.f);
            prod = 1.f;

            // ---- list1: factor = e/(1+e), groups of 4, one rcp ----
            {
                int i = 0, n4 = cnt1 & ~3;
                for (; i < n4; i += 4) {
                    float4 f0 = sL1[i], f1 = sL1[i+1], f2 = sL1[i+2], f3 = sL1[i+3];
                    float e0 = fminf(ex2f(fmaf(f0.x, X, fmaf(f0.y, Y, f0.z))), CLAMPF);
                    float e1 = fminf(ex2f(fmaf(f1.x, X, fmaf(f1.y, Y, f1.z))), CLAMPF);
                    float e2 = fminf(ex2f(fmaf(f2.x, X, fmaf(f2.y, Y, f2.z))), CLAMPF);
                    float e3 = fminf(ex2f(fmaf(f3.x, X, fmaf(f3.y, Y, f3.z))), CLAMPF);
                    float num = (e0 * e1) * (e2 * e3);
                    float den = ((1.f + e0) * (1.f + e1)) * ((1.f + e2) * (1.f + e3));
                    prod *= num * rcpaf(den);
                }
                for (; i < cnt1; i++) {
                    float4 f0 = sL1[i];
                    float e0 = fminf(ex2f(fmaf(f0.x, X, fmaf(f0.y, Y, f0.z))), CLAMPF);
                    prod *= e0 * rcpaf(1.f + e0);
                }
            }
            // ---- list2: factor = n/(n+1), n = ea+eb+ea*eb, groups of 4 ----
            {
                int i = 0, n4 = cnt2 & ~3;
                for (; i < n4; i += 4) {
                    float n[4], d[4];
                    #pragma unroll
                    for (int k = 0; k < 4; k++) {
                        float4 p  = sL2[2*(i+k)];
                        float4 qv = sL2[2*(i+k) + 1];
                        float ea = fminf(ex2f(fmaf(p.x,  X, fmaf(p.y,  Y, p.z))),  CLAMPF);
                        float eb = fminf(ex2f(fmaf(qv.x, X, fmaf(qv.y, Y, qv.z))), CLAMPF);
                        float nk = fminf(fmaf(ea, eb, ea + eb), CLAMPF);
                        n[k] = nk; d[k] = nk + 1.f;
                    }
                    float num = (n[0] * n[1]) * (n[2] * n[3]);
                    float den = (d[0] * d[1]) * (d[2] * d[3]);
                    prod *= num * rcpaf(den);
                }
                for (; i < cnt2; i++) {
                    float4 p  = sL2[2*i];
                    float4 qv = sL2[2*i + 1];
                    float ea = fminf(ex2f(fmaf(p.x,  X, fmaf(p.y,  Y, p.z))),  CLAMPF);
                    float eb = fminf(ex2f(fmaf(qv.x, X, fmaf(qv.y, Y, qv.z))), CLAMPF);
                    float nk = fminf(fmaf(ea, eb, ea + eb), CLAMPF);
                    prod *= nk * rcpaf(nk + 1.f);
                }
            }
            // ---- list3: P = (1+e0)(1+e1)(1+e2) clamped; factor=(P-1)/P ----
            {
                int i = 0, n4 = cnt3 & ~3;
                for (; i < n4; i += 4) {
                    float n[4], d[4];
                    #pragma unroll
                    for (int k = 0; k < 4; k++) {
                        float4 p0 = sL3[3*(i+k)];
                        float4 p1 = sL3[3*(i+k) + 1];
                        float4 p2 = sL3[3*(i+k) + 2];
                        float u0 = 1.f + ex2f(fmaf(p0.x, X, fmaf(p0.y, Y, p0.z)));
                        float u1 = 1.f + ex2f(fmaf(p1.x, X, fmaf(p1.y, Y, p1.z)));
                        float u2 = 1.f + ex2f(fmaf(p2.x, X, fmaf(p2.y, Y, p2.z)));
                        float P  = fminf(u0 * u1 * u2, CLAMPF);
                        n[k] = P - 1.f; d[k] = P;
                    }
                    float num = (n[0] * n[1]) * (n[2] * n[3]);
                    float den = (d[0] * d[1]) * (d[2] * d[3]);
                    prod *= num * rcpaf(den);
                }
                for (; i < cnt3; i++) {
                    float4 p0 = sL3[3*i];
                    float4 p1 = sL3[3*i + 1];
                    float4 p2 = sL3[3*i + 2];
                    float u0 = 1.f + ex2f(fmaf(p0.x, X, fmaf(p0.y, Y, p0.z)));
                    float u1 = 1.f + ex2f(fmaf(p1.x, X, fmaf(p1.y, Y, p1.z)));
                    float u2 = 1.f + ex2f(fmaf(p2.x, X, fmaf(p2.y, Y, p2.z)));
                    float P  = fminf(u0 * u1 * u2, CLAMPF);
                    prod *= (P - 1.f) * rcpaf(P);
                }
            }
        }
        g_part[z * (IMG * IMG) + pix] = prod;

        // ---------- Phase C: last chunk per tile combines --------------------
        __syncthreads();
        if (tid == 0) {
            __threadfence();
            unsigned old = atomicInc(&g_tcnt[tileIdx], SPLIT - 1);
            s_flag = (old == SPLIT - 1);
            if (s_flag) __threadfence();
        }
        __syncthreads();
        if (!s_flag) continue;

        float p = 1.f;
        #pragma unroll
        for (int zz = 0; zz < SPLIT; zz++) p *= g_part[zz * (IMG * IMG) + pix];
        int nd = g_degblk[0] + g_degblk[1] + g_degblk[2] + g_degblk[3];
        for (int i = 0; i < nd; i++) p *= 0.875f;

        float sil = 1.f - p;
        float d = sil - ref[pix];
        red[tid] = d * d;
        __syncthreads();
        #pragma unroll
        for (int s2 = 128; s2 > 0; s2 >>= 1) {
            if (tid < s2) red[tid] += red[tid + s2];
            __syncthreads();
        }

        // ---------- Phase D: last tile sums all tile losses ------------------
        if (tid == 0) {
            g_row[tileIdx] = red[0];
            __threadfence();
            unsigned old = atomicInc(&g_done, NTILES - 1);
            s_flag = (old == NTILES - 1);
            if (s_flag) __threadfence();
        }
        __syncthreads();
        if (!s_flag) continue;

        red[tid] = g_row[tid];
        __syncthreads();
        #pragma unroll
        for (int s2 = 128; s2 > 0; s2 >>= 1) {
            if (tid < s2) red[tid] += red[tid + s2];
            __syncthreads();
        }
        if (tid == 0) out[0] = red[0];
        __syncthreads();
    }
}

extern "C" void kernel_launch(void* const* d_in, const int* in_sizes, int n_in,
                              void* d_out, int out_size)
{
    const float* verts = (const float*)d_in[0];
    const int*   faces = (const int*)  d_in[1];
    const float* cam   = (const float*)d_in[2];
    const float* ref   = (const float*)d_in[3];

    prep_kernel<<<4, 256>>>(verts, faces, cam);
    render_kernel<<<NBLOCKS, 256>>>(ref, (float*)d_out);
}

// round 15
// speedup vs baseline: 1.3016x; 1.3016x over previous
#include <cuda_runtime.h>
#include <cstdint>

#define NFACES 1000
#define NPAD   1024
#define IMG    256
#define SPLIT  16
#define CHUNK  64                 // 16*64 = 1024 faces padded
#define NTILES 256
#define NITEMS (NTILES * SPLIT)
#define NBLOCKS 1024
#define CULL_T 10.0f              // frag <= 2^-10 dropped; err scales 2^-T (measured 1.9e-6 @ T=15)
#define ACT_T  (-10.0f)
#define CLAMPF 33554432.0f        // 2^25

__device__ float4   g_c0[NPAD];
__device__ float4   g_c1[NPAD];
__device__ float    g_c2[NPAD];
__device__ int      g_degblk[4];
__device__ float    g_part[SPLIT * IMG * IMG];
__device__ float    g_row[NTILES];
__device__ unsigned g_tcnt[NTILES];           // wrapping -> replay-safe
__device__ unsigned g_done;
__device__ unsigned g_qhead;

__device__ __forceinline__ float ex2f(float x) {
    float y; asm("ex2.approx.f32 %0, %1;" : "=f"(y) : "f"(x)); return y;
}
__device__ __forceinline__ float rcpaf(float x) {
    float y; asm("rcp.approx.f32 %0, %1;" : "=f"(y) : "f"(x)); return y;
}
__device__ __forceinline__ float rsqaf(float x) {
    float y; asm("rsqrt.approx.f32 %0, %1;" : "=f"(y) : "f"(x)); return y;
}

// ---------------------------------------------------------------------------
// Kernel 1: per-face prep + queue reset
// ---------------------------------------------------------------------------
__global__ void __launch_bounds__(256) prep_kernel(
    const float* __restrict__ verts,
    const int*   __restrict__ faces,
    const float* __restrict__ cam)
{
    __shared__ int wdeg[8];
    const int tid = threadIdx.x;
    const int f   = blockIdx.x * 256 + tid;

    if (blockIdx.x == 0 && tid == 0) g_qhead = 0u;

    bool deg = false;

    if (f < NFACES) {
        float ex = cam[0], ey = cam[1], ez = cam[2];
        float rz = rsqaf(ex*ex + ey*ey + ez*ez);
        float zx = -ex * rz, zy = -ey * rz, zz = -ez * rz;
        float rx = rsqaf(zz*zz + zx*zx);
        float xx = zz * rx, xz = -zx * rx;
        float yx = zy * xz;
        float yy = zz * xx - zx * xz;
        float yz = -zy * xx;

        const float w = 0.57735026918962576f;  // tan(30 deg)

        float px[3], py[3];
        #pragma unroll
        for (int k = 0; k < 3; k++) {
            int vi = faces[3 * f + k];
            float dx = verts[3 * vi + 0] - ex;
            float dy = verts[3 * vi + 1] - ey;
            float dz = verts[3 * vi + 2] - ez;
            float cx = xx * dx + xz * dz;
            float cy = yx * dx + yy * dy + yz * dz;
            float cz = zx * dx + zy * dy + zz * dz;
            float rzw = rcpaf(cz * w);
            px[k] = cx * rzw;
            py[k] = cy * rzw;
        }

        float e01x = px[1] - px[0], e01y = py[1] - py[0];
        float e02x = px[2] - px[0], e02y = py[2] - py[0];
        float area = __fmul_rn(e01x, e02y) - __fmul_rn(e01y, e02x);

        if (area == 0.f) {
            deg = true;
            g_c0[f] = make_float4(0.f, 0.f, 1e9f, 0.f);
            g_c1[f] = make_float4(0.f, 0.f, 0.f, 0.f);
            g_c2[f] = 0.f;
        } else {
            float s = (area > 0.f) ? 1.f : -1.f;
            float K = s * 144.26950408889634f;

            float A[3], B[3], C[3];
            const int ia[3] = {0, 1, 2}, ib[3] = {1, 2, 0};
            #pragma unroll
            for (int e = 0; e < 3; e++) {
                float ax = px[ib[e]] - px[ia[e]];
                float ay = py[ib[e]] - py[ia[e]];
                float rlen = rsqaf(ax*ax + ay*ay);
                float nx = -ay * rlen, ny = ax * rlen;
                A[e] = -K * nx;
                B[e] = -K * ny;
                C[e] =  K * (px[ia[e]] * nx + py[ia[e]] * ny);
            }
            g_c0[f] = make_float4(A[0], B[0], C[0], A[1]);
            g_c1[f] = make_float4(B[1], C[1], A[2], B[2]);
            g_c2[f] = C[2];
        }
    } else {
        g_c0[f] = make_float4(0.f, 0.f, 1e9f, 0.f);
        g_c1[f] = make_float4(0.f, 0.f, 0.f, 0.f);
        g_c2[f] = 0.f;
    }

    unsigned bal = __ballot_sync(0xffffffffu, deg);
    if ((tid & 31) == 0) wdeg[tid >> 5] = __popc(bal);
    __syncthreads();
    if (tid == 0) {
        int nd = 0;
        #pragma unroll
        for (int i = 0; i < 8; i++) nd += wdeg[i];
        g_degblk[blockIdx.x] = nd;
    }
}

// ---------------------------------------------------------------------------
// Kernel 2: work-stealing render with per-(face,tile) edge-activity lists.
// ---------------------------------------------------------------------------
__global__ void __launch_bounds__(256, 6) render_kernel(
    const float* __restrict__ ref,
    float*       __restrict__ out)
{
    __shared__ float4 sL1[CHUNK];          // 1 active edge: (A,B,C,_)
    __shared__ float4 sL2[CHUNK * 2];      // 2 active edges
    __shared__ float4 sL3[CHUNK * 3];      // 3 active edges
    __shared__ int    sc1[2], sc2[2], sc3[2], sz[2];
    __shared__ int    s_item, s_flag;
    __shared__ float  red[256];

    const int tid  = threadIdx.x;
    const int lane = tid & 31, wid = tid >> 5;
    const unsigned lmask = (1u << lane) - 1u;

    for (;;) {
        if (tid == 0) s_item = (int)atomicAdd(&g_qhead, 1u);
        __syncthreads();
        const int item = s_item;
        if (item >= NITEMS) return;

        const int tileIdx = item >> 4;
        const int z       = item & (SPLIT - 1);
        const int c0 = (tileIdx & 15) * 16, r0 = (tileIdx >> 4) * 16;

        const float xmin = (2.f * c0 + 1.f)        * (1.f / 256.f) - 1.f;
        const float xmax = (2.f * (c0 + 15) + 1.f) * (1.f / 256.f) - 1.f;
        const float ymax = 1.f - (2.f * r0 + 1.f)        * (1.f / 256.f);
        const float ymin = 1.f - (2.f * (r0 + 15) + 1.f) * (1.f / 256.f);

        // ---------- Phase A: cull + edge-activity classification ------------
        int  cat = 0;           // 0 dropped, 1/2/3 = #active edges
        bool zero = false;
        float4 fa, fb; float fcc = 0.f;
        float4 E0, E1, E2;
        bool a0 = false, a1 = false, a2 = false;

        if (tid < CHUNK) {
            int f = z * CHUNK + tid;
            fa = g_c0[f]; fb = g_c1[f]; fcc = g_c2[f];
            E0 = make_float4(fa.x, fa.y, fa.z, 0.f);
            E1 = make_float4(fa.w, fb.x, fb.y, 0.f);
            E2 = make_float4(fb.z, fb.w, fcc,  0.f);

            float m0, M0, m1, M1, m2, M2;
            {
                float xl = E0.x * xmin, xh = E0.x * xmax;
                float yl = E0.y * ymin, yh = E0.y * ymax;
                m0 = fminf(xl, xh) + fminf(yl, yh) + E0.z;
                M0 = fmaxf(xl, xh) + fmaxf(yl, yh) + E0.z;
            }
            {
                float xl = E1.x * xmin, xh = E1.x * xmax;
                float yl = E1.y * ymin, yh = E1.y * ymax;
                m1 = fminf(xl, xh) + fminf(yl, yh) + E1.z;
                M1 = fmaxf(xl, xh) + fmaxf(yl, yh) + E1.z;
            }
            {
                float xl = E2.x * xmin, xh = E2.x * xmax;
                float yl = E2.y * ymin, yh = E2.y * ymax;
                m2 = fminf(xl, xh) + fminf(yl, yh) + E2.z;
                M2 = fmaxf(xl, xh) + fmaxf(yl, yh) + E2.z;
            }
            float q = fmaxf(m0, 0.f) + fmaxf(m1, 0.f) + fmaxf(m2, 0.f);
            bool keep = q < CULL_T;
            if (keep) {
                a0 = M0 > ACT_T; a1 = M1 > ACT_T; a2 = M2 > ACT_T;
                int na = (int)a0 + (int)a1 + (int)a2;
                if (na == 0) zero = true;   // frag~1.0 tile-wide -> plane 0
                else cat = na;
            }
        }

        unsigned b1 = __ballot_sync(0xffffffffu, cat == 1);
        unsigned b2 = __ballot_sync(0xffffffffu, cat == 2);
        unsigned b3 = __ballot_sync(0xffffffffu, cat == 3);
        unsigned bz = __ballot_sync(0xffffffffu, zero);
        if (lane == 0 && wid < 2) {
            sc1[wid] = __popc(b1); sc2[wid] = __popc(b2);
            sc3[wid] = __popc(b3); sz[wid]  = __popc(bz);
        }
        __syncthreads();

        const int cnt1 = sc1[0] + sc1[1];
        const int cnt2 = sc2[0] + sc2[1];
        const int cnt3 = sc3[0] + sc3[1];
        const bool tile_zero = (sz[0] + sz[1]) > 0;

        if (!tile_zero) {
            if (cat == 1) {
                int off = (wid == 1 ? sc1[0] : 0) + __popc(b1 & lmask);
                sL1[off] = a0 ? E0 : (a1 ? E1 : E2);
            } else if (cat == 2) {
                int off = (wid == 1 ? sc2[0] : 0) + __popc(b2 & lmask);
                float4 p, qv;
                if (!a0)      { p = E1; qv = E2; }
                else if (!a1) { p = E0; qv = E2; }
                else          { p = E0; qv = E1; }
                sL2[2*off] = p; sL2[2*off + 1] = qv;
            } else if (cat == 3) {
                int off = (wid == 1 ? sc3[0] : 0) + __popc(b3 & lmask);
                sL3[3*off] = E0; sL3[3*off + 1] = E1; sL3[3*off + 2] = E2;
            }
        }
        __syncthreads();

        const int gc = c0 + (tid & 15);
        const int gr = r0 + (tid >> 4);
        const int pix = gr * IMG + gc;

        float prod;
        if (tile_zero) {
            prod = 0.f;                        // a face covers the tile deeply
        } else {
            const float X = (2.f * gc + 1.f) * (1.f / 256.f) - 1.f;
            const float Y = 1.f - (2.f * gr + 1.f) * (1.f / 256.f);
            prod = 1.f;

            // ---- list1: factor = e/(1+e), groups of 4, one rcp ----
            {
                int i = 0, n4 = cnt1 & ~3;
                for (; i < n4; i += 4) {
                    float4 f0 = sL1[i], f1 = sL1[i+1], f2 = sL1[i+2], f3 = sL1[i+3];
                    float e0 = fminf(ex2f(fmaf(f0.x, X, fmaf(f0.y, Y, f0.z))), CLAMPF);
                    float e1 = fminf(ex2f(fmaf(f1.x, X, fmaf(f1.y, Y, f1.z))), CLAMPF);
                    float e2 = fminf(ex2f(fmaf(f2.x, X, fmaf(f2.y, Y, f2.z))), CLAMPF);
                    float e3 = fminf(ex2f(fmaf(f3.x, X, fmaf(f3.y, Y, f3.z))), CLAMPF);
                    float num = (e0 * e1) * (e2 * e3);
                    float den = ((1.f + e0) * (1.f + e1)) * ((1.f + e2) * (1.f + e3));
                    prod *= num * rcpaf(den);
                }
                for (; i < cnt1; i++) {
                    float4 f0 = sL1[i];
                    float e0 = fminf(ex2f(fmaf(f0.x, X, fmaf(f0.y, Y, f0.z))), CLAMPF);
                    prod *= e0 * rcpaf(1.f + e0);
                }
            }
            // ---- list2: factor = n/(n+1), n = ea+eb+ea*eb, groups of 4 ----
            {
                int i = 0, n4 = cnt2 & ~3;
                for (; i < n4; i += 4) {
                    float n[4], d[4];
                    #pragma unroll
                    for (int k = 0; k < 4; k++) {
                        float4 p  = sL2[2*(i+k)];
                        float4 qv = sL2[2*(i+k) + 1];
                        float ea = fminf(ex2f(fmaf(p.x,  X, fmaf(p.y,  Y, p.z))),  CLAMPF);
                        float eb = fminf(ex2f(fmaf(qv.x, X, fmaf(qv.y, Y, qv.z))), CLAMPF);
                        float nk = fminf(fmaf(ea, eb, ea + eb), CLAMPF);
                        n[k] = nk; d[k] = nk + 1.f;
                    }
                    float num = (n[0] * n[1]) * (n[2] * n[3]);
                    float den = (d[0] * d[1]) * (d[2] * d[3]);
                    prod *= num * rcpaf(den);
                }
                for (; i < cnt2; i++) {
                    float4 p  = sL2[2*i];
                    float4 qv = sL2[2*i + 1];
                    float ea = fminf(ex2f(fmaf(p.x,  X, fmaf(p.y,  Y, p.z))),  CLAMPF);
                    float eb = fminf(ex2f(fmaf(qv.x, X, fmaf(qv.y, Y, qv.z))), CLAMPF);
                    float nk = fminf(fmaf(ea, eb, ea + eb), CLAMPF);
                    prod *= nk * rcpaf(nk + 1.f);
                }
            }
            // ---- list3: P = (1+e0)(1+e1)(1+e2) clamped; factor=(P-1)/P ----
            {
                int i = 0, n4 = cnt3 & ~3;
                for (; i < n4; i += 4) {
                    float n[4], d[4];
                    #pragma unroll
                    for (int k = 0; k < 4; k++) {
                        float4 p0 = sL3[3*(i+k)];
                        float4 p1 = sL3[3*(i+k) + 1];
                        float4 p2 = sL3[3*(i+k) + 2];
                        float u0 = 1.f + ex2f(fmaf(p0.x, X, fmaf(p0.y, Y, p0.z)));
                        float u1 = 1.f + ex2f(fmaf(p1.x, X, fmaf(p1.y, Y, p1.z)));
                        float u2 = 1.f + ex2f(fmaf(p2.x, X, fmaf(p2.y, Y, p2.z)));
                        float P  = fminf(u0 * u1 * u2, CLAMPF);
                        n[k] = P - 1.f; d[k] = P;
                    }
                    float num = (n[0] * n[1]) * (n[2] * n[3]);
                    float den = (d[0] * d[1]) * (d[2] * d[3]);
                    prod *= num * rcpaf(den);
                }
                for (; i < cnt3; i++) {
                    float4 p0 = sL3[3*i];
                    float4 p1 = sL3[3*i + 1];
                    float4 p2 = sL3[3*i + 2];
                    float u0 = 1.f + ex2f(fmaf(p0.x, X, fmaf(p0.y, Y, p0.z)));
                    float u1 = 1.f + ex2f(fmaf(p1.x, X, fmaf(p1.y, Y, p1.z)));
                    float u2 = 1.f + ex2f(fmaf(p2.x, X, fmaf(p2.y, Y, p2.z)));
                    float P  = fminf(u0 * u1 * u2, CLAMPF);
                    prod *= (P - 1.f) * rcpaf(P);
                }
            }
        }
        g_part[z * (IMG * IMG) + pix] = prod;

        // ---------- Phase C: last chunk per tile combines --------------------
        __syncthreads();
        if (tid == 0) {
            __threadfence();
            unsigned old = atomicInc(&g_tcnt[tileIdx], SPLIT - 1);
            s_flag = (old == SPLIT - 1);
            if (s_flag) __threadfence();
        }
        __syncthreads();
        if (!s_flag) continue;

        float p = 1.f;
        #pragma unroll
        for (int zz = 0; zz < SPLIT; zz++) p *= g_part[zz * (IMG * IMG) + pix];
        int nd = g_degblk[0] + g_degblk[1] + g_degblk[2] + g_degblk[3];
        for (int i = 0; i < nd; i++) p *= 0.875f;

        float sil = 1.f - p;
        float d = sil - ref[pix];
        red[tid] = d * d;
        __syncthreads();
        #pragma unroll
        for (int s2 = 128; s2 > 0; s2 >>= 1) {
            if (tid < s2) red[tid] += red[tid + s2];
            __syncthreads();
        }

        // ---------- Phase D: last tile sums all tile losses ------------------
        if (tid == 0) {
            g_row[tileIdx] = red[0];
            __threadfence();
            unsigned old = atomicInc(&g_done, NTILES - 1);
            s_flag = (old == NTILES - 1);
            if (s_flag) __threadfence();
        }
        __syncthreads();
        if (!s_flag) continue;

        red[tid] = g_row[tid];
        __syncthreads();
        #pragma unroll
        for (int s2 = 128; s2 > 0; s2 >>= 1) {
            if (tid < s2) red[tid] += red[tid + s2];
            __syncthreads();
        }
        if (tid == 0) out[0] = red[0];
        __syncthreads();
    }
}

extern "C" void kernel_launch(void* const* d_in, const int* in_sizes, int n_in,
                              void* d_out, int out_size)
{
    const float* verts = (const float*)d_in[0];
    const int*   faces = (const int*)  d_in[1];
    const float* cam   = (const float*)d_in[2];
    const float* ref   = (const float*)d_in[3];

    prep_kernel<<<4, 256>>>(verts, faces, cam);
    render_kernel<<<NBLOCKS, 256>>>(ref, (float*)d_out);
}